// round 13
// baseline (speedup 1.0000x reference)
#include <cuda_runtime.h>
#include <math.h>

// Problem constants
#define BB   2
#define TT   1024
#define LL   24
#define HH   16
#define DD   1024
#define HD   64
#define VV   50257
#define FF   4096
#define MM   (BB*TT)   // 2048 rows
#define NSPL 4         // attention split-K factor

// Scratch buffers (device globals: no allocation allowed)
__device__ float g_x  [MM * DD];       // residual stream
__device__ float g_h  [MM * DD];       // ln out / attention y
__device__ float g_qkv[MM * 3 * DD];   // qkv
__device__ float g_ffn[MM * FF];       // ffn hidden
// attention split-K partials: [split][bh][t][64] + (mx,l) per (split,bh,t)
__device__ float g_part[NSPL * BB * HH * TT * 64];   // 33.6 MB
__device__ float g_ml  [NSPL * BB * HH * TT * 2];

// ---------------------------------------------------------------------------
// Helpers
// ---------------------------------------------------------------------------
__device__ __forceinline__ unsigned f2tf32(float f) {
    unsigned u;
    asm("cvt.rna.tf32.f32 %0, %1;" : "=r"(u) : "f"(f));
    return u;
}

__device__ __forceinline__ void cp_async16(void* dst_smem, const void* src_gmem) {
    unsigned d = (unsigned)__cvta_generic_to_shared(dst_smem);
    asm volatile("cp.async.cg.shared.global [%0], [%1], 16;\n" :: "r"(d), "l"(src_gmem));
}
#define CP_COMMIT() asm volatile("cp.async.commit_group;\n" ::: "memory")
#define CP_WAIT(n)  asm volatile("cp.async.wait_group %0;\n" :: "n"(n) : "memory")

__device__ __forceinline__ void mma_tf32(float* c, const unsigned* a, const unsigned* b) {
    asm volatile(
        "mma.sync.aligned.m16n8k8.row.col.f32.tf32.tf32.f32 "
        "{%0,%1,%2,%3}, {%4,%5,%6,%7}, {%8,%9}, {%0,%1,%2,%3};"
        : "+f"(c[0]), "+f"(c[1]), "+f"(c[2]), "+f"(c[3])
        : "r"(a[0]), "r"(a[1]), "r"(a[2]), "r"(a[3]), "r"(b[0]), "r"(b[1]));
}

__device__ __forceinline__ float gelu_f(float x) {
    float x3 = x * x * x;
    return 0.5f * x * (1.0f + tanhf(0.7978845608028654f * (x + 0.044715f * x3)));
}

// ---------------------------------------------------------------------------
// Embedding
// ---------------------------------------------------------------------------
__global__ void embed_kernel(const int* __restrict__ idx,
                             const float* __restrict__ wte,
                             const float* __restrict__ wpe,
                             float* __restrict__ x) {
    int bt = blockIdx.x;
    int t  = bt % TT;
    int tok = idx[bt];
    const float* a = wte + (size_t)tok * DD;
    const float* p = wpe + (size_t)t * DD;
    float* o = x + (size_t)bt * DD;
    for (int i = threadIdx.x; i < DD; i += blockDim.x)
        o[i] = a[i] + p[i];
}

// ---------------------------------------------------------------------------
// LayerNorm
// ---------------------------------------------------------------------------
__inline__ __device__ float warp_sum(float v) {
    #pragma unroll
    for (int o = 16; o > 0; o >>= 1) v += __shfl_down_sync(0xffffffffu, v, o);
    return v;
}

__global__ void __launch_bounds__(256) ln_kernel(const float* __restrict__ x,
                                                 const float* __restrict__ w,
                                                 const float* __restrict__ b,
                                                 float* __restrict__ out) {
    int row = blockIdx.x;
    const float* xr = x + (size_t)row * DD;
    int i0 = threadIdx.x * 4;
    float4 v = *(const float4*)(xr + i0);
    float s  = v.x + v.y + v.z + v.w;
    float s2 = v.x*v.x + v.y*v.y + v.z*v.z + v.w*v.w;

    __shared__ float red1[8], red2[8];
    int wid = threadIdx.x >> 5, lid = threadIdx.x & 31;
    float ws = warp_sum(s), ws2 = warp_sum(s2);
    if (lid == 0) { red1[wid] = ws; red2[wid] = ws2; }
    __syncthreads();
    if (wid == 0) {
        float a = (lid < 8) ? red1[lid] : 0.f;
        float c = (lid < 8) ? red2[lid] : 0.f;
        a = warp_sum(a); c = warp_sum(c);
        if (lid == 0) { red1[0] = a; red2[0] = c; }
    }
    __syncthreads();
    float mean = red1[0] * (1.0f / DD);
    float var  = red2[0] * (1.0f / DD) - mean * mean;
    float inv  = rsqrtf(var + 1e-5f);

    float4 wv = *(const float4*)(w + i0);
    float4 bv = *(const float4*)(b + i0);
    float4 ov;
    ov.x = (v.x - mean) * inv * wv.x + bv.x;
    ov.y = (v.y - mean) * inv * wv.y + bv.y;
    ov.z = (v.z - mean) * inv * wv.z + bv.z;
    ov.w = (v.w - mean) * inv * wv.w + bv.w;
    *(float4*)(out + (size_t)row * DD + i0) = ov;
}

// ---------------------------------------------------------------------------
// TF32 tensor-core GEMM (NN): C[M,N] = A[M,K] @ W[K,N] (+bias)(+gelu|+res)
// BM=BN=128, BK=16, 256 threads (8 warps, warp tile 64x32), cp.async double
// buffer. (R9/R12 proven version.)
// ---------------------------------------------------------------------------
__global__ void __launch_bounds__(256) gemm_tf32_nn(
    const float* __restrict__ A, const float* __restrict__ W,
    const float* __restrict__ bias, const float* __restrict__ res,
    float* __restrict__ C, int M, int N, int K, int epi)
{
    __shared__ float As[2][128][20];   // [m][k]
    __shared__ float Bs[2][16][136];   // [k][n]

    const int m0 = blockIdx.x * 128;
    const int n0 = blockIdx.y * 128;
    const int tid  = threadIdx.x;
    const int lane = tid & 31;
    const int warp = tid >> 5;
    const int warpM = warp & 1;
    const int warpN = warp >> 1;
    const int Ti = lane >> 2;
    const int Tj = lane & 3;

    const int arow = tid >> 2;
    const int akq  = (tid & 3) * 4;
    const int brow = tid >> 5;
    const int bnq  = (tid & 31) * 4;

    float acc[4][4][4];
    #pragma unroll
    for (int i = 0; i < 4; i++)
        #pragma unroll
        for (int j = 0; j < 4; j++)
            #pragma unroll
            for (int r = 0; r < 4; r++) acc[i][j][r] = 0.f;

    const int nk = K / 16;

    {
        const float* a0p = A + (size_t)(m0 + arow) * K + akq;
        cp_async16(&As[0][arow][akq],      a0p);
        cp_async16(&As[0][arow + 64][akq], a0p + (size_t)64 * K);
        const float* b0p = W + (size_t)brow * N + n0 + bnq;
        cp_async16(&Bs[0][brow][bnq],      b0p);
        cp_async16(&Bs[0][brow + 8][bnq],  b0p + (size_t)8 * N);
        CP_COMMIT();
    }

    for (int kt = 0; kt < nk; kt++) {
        if (kt + 1 < nk) {
            int s = (kt + 1) & 1;
            int k0 = (kt + 1) * 16;
            const float* ap = A + (size_t)(m0 + arow) * K + k0 + akq;
            cp_async16(&As[s][arow][akq],      ap);
            cp_async16(&As[s][arow + 64][akq], ap + (size_t)64 * K);
            const float* bp = W + (size_t)(k0 + brow) * N + n0 + bnq;
            cp_async16(&Bs[s][brow][bnq],      bp);
            cp_async16(&Bs[s][brow + 8][bnq],  bp + (size_t)8 * N);
            CP_COMMIT();
            CP_WAIT(1);
        } else {
            CP_WAIT(0);
        }
        __syncthreads();

        const int s = kt & 1;
        #pragma unroll
        for (int ks = 0; ks < 2; ks++) {
            const int k0 = ks * 8;
            unsigned af[4][4], bf[4][2];
            #pragma unroll
            for (int mi = 0; mi < 4; mi++) {
                int rb = warpM * 64 + mi * 16;
                af[mi][0] = f2tf32(As[s][rb + Ti][k0 + Tj]);
                af[mi][1] = f2tf32(As[s][rb + Ti + 8][k0 + Tj]);
                af[mi][2] = f2tf32(As[s][rb + Ti][k0 + Tj + 4]);
                af[mi][3] = f2tf32(As[s][rb + Ti + 8][k0 + Tj + 4]);
            }
            #pragma unroll
            for (int nj = 0; nj < 4; nj++) {
                int cb = warpN * 32 + nj * 8;
                bf[nj][0] = f2tf32(Bs[s][k0 + Tj][cb + Ti]);
                bf[nj][1] = f2tf32(Bs[s][k0 + Tj + 4][cb + Ti]);
            }
            #pragma unroll
            for (int mi = 0; mi < 4; mi++)
                #pragma unroll
                for (int nj = 0; nj < 4; nj++)
                    mma_tf32(acc[mi][nj], af[mi], bf[nj]);
        }
        __syncthreads();
    }

    #pragma unroll
    for (int mi = 0; mi < 4; mi++) {
        const int r = m0 + warpM * 64 + mi * 16 + Ti;
        #pragma unroll
        for (int nj = 0; nj < 4; nj++) {
            const int c = n0 + warpN * 32 + nj * 8 + 2 * Tj;
            float v0 = acc[mi][nj][0], v1 = acc[mi][nj][1];
            float v2 = acc[mi][nj][2], v3 = acc[mi][nj][3];
            if (bias) {
                float b0 = bias[c], b1 = bias[c + 1];
                v0 += b0; v1 += b1; v2 += b0; v3 += b1;
            }
            if (epi == 1) {
                v0 = gelu_f(v0); v1 = gelu_f(v1); v2 = gelu_f(v2); v3 = gelu_f(v3);
            } else if (epi == 2) {
                v0 += res[(size_t)r * N + c];
                v1 += res[(size_t)r * N + c + 1];
                v2 += res[(size_t)(r + 8) * N + c];
                v3 += res[(size_t)(r + 8) * N + c + 1];
            }
            *(float2*)&C[(size_t)r * N + c]       = make_float2(v0, v1);
            *(float2*)&C[(size_t)(r + 8) * N + c] = make_float2(v2, v3);
        }
    }
}

// ---------------------------------------------------------------------------
// TF32 GEMM (NN), BM=64 variant: for N=1024 launches (aproj, proj) whose
// BM=128 grid is only 128 blocks on 148 SMs (single partial wave). Same 8
// warps, same BK=16 pipeline, same smem addressing; warp tile 32x32,
// acc[2][4][4] (~90 regs -> 2+ blocks/SM). Grid = (M/64, N/128) = 256 blocks.
// Per-element K accumulation order identical to BM=128 version.
// ---------------------------------------------------------------------------
__global__ void __launch_bounds__(256) gemm_tf32_nn64(
    const float* __restrict__ A, const float* __restrict__ W,
    const float* __restrict__ bias, const float* __restrict__ res,
    float* __restrict__ C, int M, int N, int K, int epi)
{
    __shared__ float As[2][64][20];    // [m][k]
    __shared__ float Bs[2][16][136];   // [k][n]

    const int m0 = blockIdx.x * 64;
    const int n0 = blockIdx.y * 128;
    const int tid  = threadIdx.x;
    const int lane = tid & 31;
    const int warp = tid >> 5;
    const int warpM = warp & 1;        // 2 warps over M (32 each)
    const int warpN = warp >> 1;       // 4 warps over N (32 each)
    const int Ti = lane >> 2;
    const int Tj = lane & 3;

    const int arow = tid >> 2;         // 0..63 (one row each)
    const int akq  = (tid & 3) * 4;
    const int brow = tid >> 5;
    const int bnq  = (tid & 31) * 4;

    float acc[2][4][4];
    #pragma unroll
    for (int i = 0; i < 2; i++)
        #pragma unroll
        for (int j = 0; j < 4; j++)
            #pragma unroll
            for (int r = 0; r < 4; r++) acc[i][j][r] = 0.f;

    const int nk = K / 16;

    {
        cp_async16(&As[0][arow][akq], A + (size_t)(m0 + arow) * K + akq);
        const float* b0p = W + (size_t)brow * N + n0 + bnq;
        cp_async16(&Bs[0][brow][bnq],     b0p);
        cp_async16(&Bs[0][brow + 8][bnq], b0p + (size_t)8 * N);
        CP_COMMIT();
    }

    for (int kt = 0; kt < nk; kt++) {
        if (kt + 1 < nk) {
            int s = (kt + 1) & 1;
            int k0 = (kt + 1) * 16;
            cp_async16(&As[s][arow][akq], A + (size_t)(m0 + arow) * K + k0 + akq);
            const float* bp = W + (size_t)(k0 + brow) * N + n0 + bnq;
            cp_async16(&Bs[s][brow][bnq],     bp);
            cp_async16(&Bs[s][brow + 8][bnq], bp + (size_t)8 * N);
            CP_COMMIT();
            CP_WAIT(1);
        } else {
            CP_WAIT(0);
        }
        __syncthreads();

        const int s = kt & 1;
        #pragma unroll
        for (int ks = 0; ks < 2; ks++) {
            const int k0 = ks * 8;
            unsigned af[2][4], bf[4][2];
            #pragma unroll
            for (int mi = 0; mi < 2; mi++) {
                int rb = warpM * 32 + mi * 16;
                af[mi][0] = f2tf32(As[s][rb + Ti][k0 + Tj]);
                af[mi][1] = f2tf32(As[s][rb + Ti + 8][k0 + Tj]);
                af[mi][2] = f2tf32(As[s][rb + Ti][k0 + Tj + 4]);
                af[mi][3] = f2tf32(As[s][rb + Ti + 8][k0 + Tj + 4]);
            }
            #pragma unroll
            for (int nj = 0; nj < 4; nj++) {
                int cb = warpN * 32 + nj * 8;
                bf[nj][0] = f2tf32(Bs[s][k0 + Tj][cb + Ti]);
                bf[nj][1] = f2tf32(Bs[s][k0 + Tj + 4][cb + Ti]);
            }
            #pragma unroll
            for (int mi = 0; mi < 2; mi++)
                #pragma unroll
                for (int nj = 0; nj < 4; nj++)
                    mma_tf32(acc[mi][nj], af[mi], bf[nj]);
        }
        __syncthreads();
    }

    #pragma unroll
    for (int mi = 0; mi < 2; mi++) {
        const int r = m0 + warpM * 32 + mi * 16 + Ti;
        #pragma unroll
        for (int nj = 0; nj < 4; nj++) {
            const int c = n0 + warpN * 32 + nj * 8 + 2 * Tj;
            float v0 = acc[mi][nj][0], v1 = acc[mi][nj][1];
            float v2 = acc[mi][nj][2], v3 = acc[mi][nj][3];
            if (bias) {
                float b0 = bias[c], b1 = bias[c + 1];
                v0 += b0; v1 += b1; v2 += b0; v3 += b1;
            }
            if (epi == 1) {
                v0 = gelu_f(v0); v1 = gelu_f(v1); v2 = gelu_f(v2); v3 = gelu_f(v3);
            } else if (epi == 2) {
                v0 += res[(size_t)r * N + c];
                v1 += res[(size_t)r * N + c + 1];
                v2 += res[(size_t)(r + 8) * N + c];
                v3 += res[(size_t)(r + 8) * N + c + 1];
            }
            *(float2*)&C[(size_t)r * N + c]       = make_float2(v0, v1);
            *(float2*)&C[(size_t)(r + 8) * N + c] = make_float2(v2, v3);
        }
    }
}

// ---------------------------------------------------------------------------
// TF32 GEMM (NT): C[M,N] = A[M,K] @ W[N,K]^T  (tied lm_head; R9 proven)
// ---------------------------------------------------------------------------
__global__ void __launch_bounds__(256) gemm_tf32_nt(
    const float* __restrict__ A, const float* __restrict__ W,
    float* __restrict__ C, int M, int N, int K)
{
    __shared__ float As[2][128][20];
    __shared__ float Bs[2][128][20];   // [n][k]

    const int m0 = blockIdx.x * 128;
    const int n0 = blockIdx.y * 128;
    const int tid  = threadIdx.x;
    const int lane = tid & 31;
    const int warp = tid >> 5;
    const int warpM = warp & 1;
    const int warpN = warp >> 1;
    const int Ti = lane >> 2;
    const int Tj = lane & 3;

    const int arow = tid >> 2;            // 0..63
    const int akq  = (tid & 3) * 4;       // 0,4,8,12

    int nB0 = n0 + arow;       if (nB0 >= N) nB0 = N - 1;
    int nB1 = n0 + arow + 64;  if (nB1 >= N) nB1 = N - 1;

    float acc[4][4][4];
    #pragma unroll
    for (int i = 0; i < 4; i++)
        #pragma unroll
        for (int j = 0; j < 4; j++)
            #pragma unroll
            for (int r = 0; r < 4; r++) acc[i][j][r] = 0.f;

    const int nk = K / 16;

    {
        const float* ap = A + (size_t)(m0 + arow) * K + akq;
        cp_async16(&As[0][arow][akq],      ap);
        cp_async16(&As[0][arow + 64][akq], ap + (size_t)64 * K);
        cp_async16(&Bs[0][arow][akq],      W + (size_t)nB0 * K + akq);
        cp_async16(&Bs[0][arow + 64][akq], W + (size_t)nB1 * K + akq);
        CP_COMMIT();
    }

    for (int kt = 0; kt < nk; kt++) {
        if (kt + 1 < nk) {
            int s = (kt + 1) & 1;
            int k0 = (kt + 1) * 16;
            const float* ap = A + (size_t)(m0 + arow) * K + k0 + akq;
            cp_async16(&As[s][arow][akq],      ap);
            cp_async16(&As[s][arow + 64][akq], ap + (size_t)64 * K);
            cp_async16(&Bs[s][arow][akq],      W + (size_t)nB0 * K + k0 + akq);
            cp_async16(&Bs[s][arow + 64][akq], W + (size_t)nB1 * K + k0 + akq);
            CP_COMMIT();
            CP_WAIT(1);
        } else {
            CP_WAIT(0);
        }
        __syncthreads();

        const int s = kt & 1;
        #pragma unroll
        for (int ks = 0; ks < 2; ks++) {
            const int k0 = ks * 8;
            unsigned af[4][4], bf[4][2];
            #pragma unroll
            for (int mi = 0; mi < 4; mi++) {
                int rb = warpM * 64 + mi * 16;
                af[mi][0] = f2tf32(As[s][rb + Ti][k0 + Tj]);
                af[mi][1] = f2tf32(As[s][rb + Ti + 8][k0 + Tj]);
                af[mi][2] = f2tf32(As[s][rb + Ti][k0 + Tj + 4]);
                af[mi][3] = f2tf32(As[s][rb + Ti + 8][k0 + Tj + 4]);
            }
            #pragma unroll
            for (int nj = 0; nj < 4; nj++) {
                int cb = warpN * 32 + nj * 8;
                bf[nj][0] = f2tf32(Bs[s][cb + Ti][k0 + Tj]);
                bf[nj][1] = f2tf32(Bs[s][cb + Ti][k0 + Tj + 4]);
            }
            #pragma unroll
            for (int mi = 0; mi < 4; mi++)
                #pragma unroll
                for (int nj = 0; nj < 4; nj++)
                    mma_tf32(acc[mi][nj], af[mi], bf[nj]);
        }
        __syncthreads();
    }

    #pragma unroll
    for (int mi = 0; mi < 4; mi++) {
        const int r = m0 + warpM * 64 + mi * 16 + Ti;
        #pragma unroll
        for (int nj = 0; nj < 4; nj++) {
            const int c = n0 + warpN * 32 + nj * 8 + 2 * Tj;
            if (c < N) {
                C[(size_t)r * N + c]       = acc[mi][nj][0];
                C[(size_t)(r + 8) * N + c] = acc[mi][nj][2];
            }
            if (c + 1 < N) {
                C[(size_t)r * N + c + 1]       = acc[mi][nj][1];
                C[(size_t)(r + 8) * N + c + 1] = acc[mi][nj][3];
            }
        }
    }
}

// ---------------------------------------------------------------------------
// Causal flash attention, split-K partials. grid (TT/AQ, B*H, NSPL).
// (R11/R12 proven version.)
// ---------------------------------------------------------------------------
#define AQ 64   // queries (=threads) per block
__global__ void __launch_bounds__(AQ) attn_partial(const float* __restrict__ qkv,
                                                   float* __restrict__ part,
                                                   float* __restrict__ ml)
{
    const int bh = blockIdx.y;
    const int b  = bh / HH;
    const int h  = bh % HH;
    const int qi = (gridDim.x - 1) - blockIdx.x;   // heavy blocks first
    const int sp = blockIdx.z;
    const int t  = qi * AQ + threadIdx.x;
    const float scale = 0.125f;  // 1/sqrt(64)

    const int ntiles = (qi * AQ + AQ) / 32;        // total causal key tiles
    const int q4 = (ntiles + NSPL - 1) / NSPL;
    int tb = sp * q4;       if (tb > ntiles) tb = ntiles;
    int te = (sp + 1) * q4; if (te > ntiles) te = ntiles;
    const int kb_begin = tb * 32;
    const int kb_end   = te * 32;

    float q[64];
    {
        const float* qp = qkv + (size_t)(b * TT + t) * (3 * DD) + h * HD;
        #pragma unroll
        for (int i = 0; i < 64; i += 4) {
            float4 v = *(const float4*)(qp + i);
            q[i + 0] = v.x * scale; q[i + 1] = v.y * scale;
            q[i + 2] = v.z * scale; q[i + 3] = v.w * scale;
        }
    }
    float acc[64];
    #pragma unroll
    for (int i = 0; i < 64; i++) acc[i] = 0.f;
    float mx = -1e30f, l = 0.f;

    __shared__ float Ks[32][64];
    __shared__ float Vs[32][64];

    for (int kb = kb_begin; kb < kb_end; kb += 32) {
        #pragma unroll
        for (int s = 0; s < 8; s++) {
            int f = threadIdx.x + s * AQ;    // 0..511
            int r = f >> 4;
            int c = (f & 15) * 4;
            const float* kp = qkv + (size_t)(b * TT + kb + r) * (3 * DD) + DD + h * HD + c;
            *(float4*)&Ks[r][c] = *(const float4*)kp;
            *(float4*)&Vs[r][c] = *(const float4*)(kp + DD);
        }
        __syncthreads();

        int jn = t - kb + 1;                 // valid keys in this 32-tile
        if (jn > 32) jn = 32;
        for (int j0 = 0; j0 < 32; j0 += 8) {
            if (j0 >= jn) break;
            float sc[8];
            #pragma unroll
            for (int j = 0; j < 8; j++) {
                const float* kr = &Ks[j0 + j][0];
                float a0 = 0.f, a1 = 0.f, a2 = 0.f, a3 = 0.f;
                #pragma unroll
                for (int i = 0; i < 64; i += 16) {
                    float4 k0 = *(const float4*)(kr + i);
                    float4 k1 = *(const float4*)(kr + i + 4);
                    float4 k2 = *(const float4*)(kr + i + 8);
                    float4 k3 = *(const float4*)(kr + i + 12);
                    a0 = fmaf(q[i+ 0], k0.x, a0); a0 = fmaf(q[i+ 1], k0.y, a0);
                    a0 = fmaf(q[i+ 2], k0.z, a0); a0 = fmaf(q[i+ 3], k0.w, a0);
                    a1 = fmaf(q[i+ 4], k1.x, a1); a1 = fmaf(q[i+ 5], k1.y, a1);
                    a1 = fmaf(q[i+ 6], k1.z, a1); a1 = fmaf(q[i+ 7], k1.w, a1);
                    a2 = fmaf(q[i+ 8], k2.x, a2); a2 = fmaf(q[i+ 9], k2.y, a2);
                    a2 = fmaf(q[i+10], k2.z, a2); a2 = fmaf(q[i+11], k2.w, a2);
                    a3 = fmaf(q[i+12], k3.x, a3); a3 = fmaf(q[i+13], k3.y, a3);
                    a3 = fmaf(q[i+14], k3.z, a3); a3 = fmaf(q[i+15], k3.w, a3);
                }
                sc[j] = (a0 + a1) + (a2 + a3);
                if (kb + j0 + j > t) sc[j] = -1e30f;   // causal mask
            }
            float mt = sc[0];
            #pragma unroll
            for (int j = 1; j < 8; j++) mt = fmaxf(mt, sc[j]);
            if (mt > mx) {
                float corr = __expf(mx - mt);
                l *= corr;
                #pragma unroll
                for (int i = 0; i < 64; i++) acc[i] *= corr;
                mx = mt;
            }
            float p[8];
            #pragma unroll
            for (int j = 0; j < 8; j++) {
                p[j] = __expf(sc[j] - mx);
                l += p[j];
            }
            #pragma unroll
            for (int j = 0; j < 8; j++) {
                const float* vr = &Vs[j0 + j][0];
                #pragma unroll
                for (int i = 0; i < 64; i += 4) {
                    float4 vv = *(const float4*)(vr + i);
                    acc[i + 0] = fmaf(p[j], vv.x, acc[i + 0]);
                    acc[i + 1] = fmaf(p[j], vv.y, acc[i + 1]);
                    acc[i + 2] = fmaf(p[j], vv.z, acc[i + 2]);
                    acc[i + 3] = fmaf(p[j], vv.w, acc[i + 3]);
                }
            }
        }
        __syncthreads();
    }

    // write unnormalized partial + (mx, l)
    const size_t base = (size_t)(sp * BB * HH + bh) * TT + t;
    float* pp = part + base * 64;
    #pragma unroll
    for (int i = 0; i < 64; i += 4) {
        float4 o;
        o.x = acc[i + 0]; o.y = acc[i + 1];
        o.z = acc[i + 2]; o.w = acc[i + 3];
        *(float4*)(pp + i) = o;
    }
    ml[base * 2]     = mx;
    ml[base * 2 + 1] = l;
}

// ---------------------------------------------------------------------------
// Merge the NSPL split-K partials (exact flash combine).
// ---------------------------------------------------------------------------
__global__ void __launch_bounds__(256) attn_merge(const float* __restrict__ part,
                                                  const float* __restrict__ ml,
                                                  float* __restrict__ y)
{
    int idx = blockIdx.x * 256 + threadIdx.x;   // 0 .. B*H*T*16-1
    int d4  = (idx & 15) * 4;
    int tt  = (idx >> 4) & (TT - 1);
    int bh  = idx >> 14;
    int b   = bh / HH;
    int h   = bh % HH;

    size_t base[NSPL];
    float ms[NSPL], ls[NSPL];
    float m = -1e30f;
    #pragma unroll
    for (int s = 0; s < NSPL; s++) {
        base[s] = (size_t)(s * BB * HH + bh) * TT + tt;
        ms[s] = ml[base[s] * 2];
        ls[s] = ml[base[s] * 2 + 1];
        m = fmaxf(m, ms[s]);
    }
    float denom = 0.f;
    float4 o = make_float4(0.f, 0.f, 0.f, 0.f);
    #pragma unroll
    for (int s = 0; s < NSPL; s++) {
        float w = __expf(ms[s] - m);
        denom += w * ls[s];
        float4 a = *(const float4*)(part + base[s] * 64 + d4);
        o.x += w * a.x; o.y += w * a.y; o.z += w * a.z; o.w += w * a.w;
    }
    float inv = 1.f / denom;
    o.x *= inv; o.y *= inv; o.z *= inv; o.w *= inv;
    *(float4*)(y + (size_t)(b * TT + tt) * DD + h * HD + d4) = o;
}

// ---------------------------------------------------------------------------
// Host launcher
// ---------------------------------------------------------------------------
extern "C" void kernel_launch(void* const* d_in, const int* in_sizes, int n_in,
                              void* d_out, int out_size)
{
    const int*   idx   = (const int*)  d_in[0];
    const float* wte   = (const float*)d_in[1];
    const float* wpe   = (const float*)d_in[2];
    const float* ln1w  = (const float*)d_in[3];
    const float* ln1b  = (const float*)d_in[4];
    const float* attnw = (const float*)d_in[5];
    const float* attnb = (const float*)d_in[6];
    const float* apw   = (const float*)d_in[7];
    const float* apb   = (const float*)d_in[8];
    const float* ln2w  = (const float*)d_in[9];
    const float* ln2b  = (const float*)d_in[10];
    const float* fcw   = (const float*)d_in[11];
    const float* fcb   = (const float*)d_in[12];
    const float* pw    = (const float*)d_in[13];
    const float* pb    = (const float*)d_in[14];
    const float* lnfw  = (const float*)d_in[15];
    const float* lnfb  = (const float*)d_in[16];
    float* out = (float*)d_out;

    float *x, *h, *qkv, *ffn, *part, *ml;
    cudaGetSymbolAddress((void**)&x,    g_x);
    cudaGetSymbolAddress((void**)&h,    g_h);
    cudaGetSymbolAddress((void**)&qkv,  g_qkv);
    cudaGetSymbolAddress((void**)&ffn,  g_ffn);
    cudaGetSymbolAddress((void**)&part, g_part);
    cudaGetSymbolAddress((void**)&ml,   g_ml);

    embed_kernel<<<MM, 256>>>(idx, wte, wpe, x);

    for (int l = 0; l < LL; l++) {
        ln_kernel<<<MM, 256>>>(x, ln1w + (size_t)l * DD, ln1b + (size_t)l * DD, h);
        // QKV: [M,D] @ [D,3D] + bias  (384 blocks: BM=128)
        gemm_tf32_nn<<<dim3(MM / 128, 3 * DD / 128), 256>>>(
            h, attnw + (size_t)l * DD * 3 * DD, attnb + (size_t)l * 3 * DD,
            nullptr, qkv, MM, 3 * DD, DD, 0);
        // attention: split-K partials + exact merge
        attn_partial<<<dim3(TT / AQ, BB * HH, NSPL), AQ>>>(qkv, part, ml);
        attn_merge<<<BB * HH * TT * 16 / 256, 256>>>(part, ml, h);
        // attn proj: x = x + y @ pw + pb  (N=1024 -> BM=64: 256 blocks)
        gemm_tf32_nn64<<<dim3(MM / 64, DD / 128), 256>>>(
            h, apw + (size_t)l * DD * DD, apb + (size_t)l * DD,
            x, x, MM, DD, DD, 2);
        ln_kernel<<<MM, 256>>>(x, ln2w + (size_t)l * DD, ln2b + (size_t)l * DD, h);
        // FC + gelu  (512 blocks: BM=128)
        gemm_tf32_nn<<<dim3(MM / 128, FF / 128), 256>>>(
            h, fcw + (size_t)l * DD * FF, fcb + (size_t)l * FF,
            nullptr, ffn, MM, FF, DD, 1);
        // proj: x = x + ffn @ ow + ob  (N=1024 -> BM=64: 256 blocks)
        gemm_tf32_nn64<<<dim3(MM / 64, DD / 128), 256>>>(
            ffn, pw + (size_t)l * FF * DD, pb + (size_t)l * DD,
            x, x, MM, DD, FF, 2);
    }

    ln_kernel<<<MM, 256>>>(x, lnfw, lnfb, h);
    gemm_tf32_nt<<<dim3(MM / 128, (VV + 127) / 128), 256>>>(
        h, wte, out, MM, VV, DD);
}

// round 14
// speedup vs baseline: 1.0118x; 1.0118x over previous
#include <cuda_runtime.h>
#include <math.h>

// Problem constants
#define BB   2
#define TT   1024
#define LL   24
#define HH   16
#define DD   1024
#define HD   64
#define VV   50257
#define FF   4096
#define MM   (BB*TT)   // 2048 rows
#define NSPL 8         // attention split-K factor

// Scratch buffers (device globals: no allocation allowed)
__device__ float g_x  [MM * DD];       // residual stream
__device__ float g_h  [MM * DD];       // ln out / attention y
__device__ float g_qkv[MM * 3 * DD];   // qkv
__device__ float g_ffn[MM * FF];       // ffn hidden
// attention split-K partials: [split][bh][t][64] + (mx,l) per (split,bh,t)
__device__ float g_part[NSPL * BB * HH * TT * 64];   // 67 MB
__device__ float g_ml  [NSPL * BB * HH * TT * 2];

// ---------------------------------------------------------------------------
// Helpers
// ---------------------------------------------------------------------------
__device__ __forceinline__ unsigned f2tf32(float f) {
    unsigned u;
    asm("cvt.rna.tf32.f32 %0, %1;" : "=r"(u) : "f"(f));
    return u;
}

__device__ __forceinline__ void cp_async16(void* dst_smem, const void* src_gmem) {
    unsigned d = (unsigned)__cvta_generic_to_shared(dst_smem);
    asm volatile("cp.async.cg.shared.global [%0], [%1], 16;\n" :: "r"(d), "l"(src_gmem));
}
#define CP_COMMIT() asm volatile("cp.async.commit_group;\n" ::: "memory")
#define CP_WAIT(n)  asm volatile("cp.async.wait_group %0;\n" :: "n"(n) : "memory")

__device__ __forceinline__ void mma_tf32(float* c, const unsigned* a, const unsigned* b) {
    asm volatile(
        "mma.sync.aligned.m16n8k8.row.col.f32.tf32.tf32.f32 "
        "{%0,%1,%2,%3}, {%4,%5,%6,%7}, {%8,%9}, {%0,%1,%2,%3};"
        : "+f"(c[0]), "+f"(c[1]), "+f"(c[2]), "+f"(c[3])
        : "r"(a[0]), "r"(a[1]), "r"(a[2]), "r"(a[3]), "r"(b[0]), "r"(b[1]));
}

__device__ __forceinline__ float gelu_f(float x) {
    float x3 = x * x * x;
    return 0.5f * x * (1.0f + tanhf(0.7978845608028654f * (x + 0.044715f * x3)));
}

// ---------------------------------------------------------------------------
// Embedding
// ---------------------------------------------------------------------------
__global__ void embed_kernel(const int* __restrict__ idx,
                             const float* __restrict__ wte,
                             const float* __restrict__ wpe,
                             float* __restrict__ x) {
    int bt = blockIdx.x;
    int t  = bt % TT;
    int tok = idx[bt];
    const float* a = wte + (size_t)tok * DD;
    const float* p = wpe + (size_t)t * DD;
    float* o = x + (size_t)bt * DD;
    for (int i = threadIdx.x; i < DD; i += blockDim.x)
        o[i] = a[i] + p[i];
}

// ---------------------------------------------------------------------------
// LayerNorm
// ---------------------------------------------------------------------------
__inline__ __device__ float warp_sum(float v) {
    #pragma unroll
    for (int o = 16; o > 0; o >>= 1) v += __shfl_down_sync(0xffffffffu, v, o);
    return v;
}

__global__ void __launch_bounds__(256) ln_kernel(const float* __restrict__ x,
                                                 const float* __restrict__ w,
                                                 const float* __restrict__ b,
                                                 float* __restrict__ out) {
    int row = blockIdx.x;
    const float* xr = x + (size_t)row * DD;
    int i0 = threadIdx.x * 4;
    float4 v = *(const float4*)(xr + i0);
    float s  = v.x + v.y + v.z + v.w;
    float s2 = v.x*v.x + v.y*v.y + v.z*v.z + v.w*v.w;

    __shared__ float red1[8], red2[8];
    int wid = threadIdx.x >> 5, lid = threadIdx.x & 31;
    float ws = warp_sum(s), ws2 = warp_sum(s2);
    if (lid == 0) { red1[wid] = ws; red2[wid] = ws2; }
    __syncthreads();
    if (wid == 0) {
        float a = (lid < 8) ? red1[lid] : 0.f;
        float c = (lid < 8) ? red2[lid] : 0.f;
        a = warp_sum(a); c = warp_sum(c);
        if (lid == 0) { red1[0] = a; red2[0] = c; }
    }
    __syncthreads();
    float mean = red1[0] * (1.0f / DD);
    float var  = red2[0] * (1.0f / DD) - mean * mean;
    float inv  = rsqrtf(var + 1e-5f);

    float4 wv = *(const float4*)(w + i0);
    float4 bv = *(const float4*)(b + i0);
    float4 ov;
    ov.x = (v.x - mean) * inv * wv.x + bv.x;
    ov.y = (v.y - mean) * inv * wv.y + bv.y;
    ov.z = (v.z - mean) * inv * wv.z + bv.z;
    ov.w = (v.w - mean) * inv * wv.w + bv.w;
    *(float4*)(out + (size_t)row * DD + i0) = ov;
}

// ---------------------------------------------------------------------------
// TF32 tensor-core GEMM (NN): C[M,N] = A[M,K] @ W[K,N] (+bias)(+gelu|+res)
// BM=BN=128, BK=16, 256 threads (8 warps, warp tile 64x32), cp.async double
// buffer. (R9/R12 proven version — local optimum, do not perturb.)
// ---------------------------------------------------------------------------
__global__ void __launch_bounds__(256) gemm_tf32_nn(
    const float* __restrict__ A, const float* __restrict__ W,
    const float* __restrict__ bias, const float* __restrict__ res,
    float* __restrict__ C, int M, int N, int K, int epi)
{
    __shared__ float As[2][128][20];   // [m][k]
    __shared__ float Bs[2][16][136];   // [k][n]

    const int m0 = blockIdx.x * 128;
    const int n0 = blockIdx.y * 128;
    const int tid  = threadIdx.x;
    const int lane = tid & 31;
    const int warp = tid >> 5;
    const int warpM = warp & 1;
    const int warpN = warp >> 1;
    const int Ti = lane >> 2;
    const int Tj = lane & 3;

    const int arow = tid >> 2;
    const int akq  = (tid & 3) * 4;
    const int brow = tid >> 5;
    const int bnq  = (tid & 31) * 4;

    float acc[4][4][4];
    #pragma unroll
    for (int i = 0; i < 4; i++)
        #pragma unroll
        for (int j = 0; j < 4; j++)
            #pragma unroll
            for (int r = 0; r < 4; r++) acc[i][j][r] = 0.f;

    const int nk = K / 16;

    {
        const float* a0p = A + (size_t)(m0 + arow) * K + akq;
        cp_async16(&As[0][arow][akq],      a0p);
        cp_async16(&As[0][arow + 64][akq], a0p + (size_t)64 * K);
        const float* b0p = W + (size_t)brow * N + n0 + bnq;
        cp_async16(&Bs[0][brow][bnq],      b0p);
        cp_async16(&Bs[0][brow + 8][bnq],  b0p + (size_t)8 * N);
        CP_COMMIT();
    }

    for (int kt = 0; kt < nk; kt++) {
        if (kt + 1 < nk) {
            int s = (kt + 1) & 1;
            int k0 = (kt + 1) * 16;
            const float* ap = A + (size_t)(m0 + arow) * K + k0 + akq;
            cp_async16(&As[s][arow][akq],      ap);
            cp_async16(&As[s][arow + 64][akq], ap + (size_t)64 * K);
            const float* bp = W + (size_t)(k0 + brow) * N + n0 + bnq;
            cp_async16(&Bs[s][brow][bnq],      bp);
            cp_async16(&Bs[s][brow + 8][bnq],  bp + (size_t)8 * N);
            CP_COMMIT();
            CP_WAIT(1);
        } else {
            CP_WAIT(0);
        }
        __syncthreads();

        const int s = kt & 1;
        #pragma unroll
        for (int ks = 0; ks < 2; ks++) {
            const int k0 = ks * 8;
            unsigned af[4][4], bf[4][2];
            #pragma unroll
            for (int mi = 0; mi < 4; mi++) {
                int rb = warpM * 64 + mi * 16;
                af[mi][0] = f2tf32(As[s][rb + Ti][k0 + Tj]);
                af[mi][1] = f2tf32(As[s][rb + Ti + 8][k0 + Tj]);
                af[mi][2] = f2tf32(As[s][rb + Ti][k0 + Tj + 4]);
                af[mi][3] = f2tf32(As[s][rb + Ti + 8][k0 + Tj + 4]);
            }
            #pragma unroll
            for (int nj = 0; nj < 4; nj++) {
                int cb = warpN * 32 + nj * 8;
                bf[nj][0] = f2tf32(Bs[s][k0 + Tj][cb + Ti]);
                bf[nj][1] = f2tf32(Bs[s][k0 + Tj + 4][cb + Ti]);
            }
            #pragma unroll
            for (int mi = 0; mi < 4; mi++)
                #pragma unroll
                for (int nj = 0; nj < 4; nj++)
                    mma_tf32(acc[mi][nj], af[mi], bf[nj]);
        }
        __syncthreads();
    }

    #pragma unroll
    for (int mi = 0; mi < 4; mi++) {
        const int r = m0 + warpM * 64 + mi * 16 + Ti;
        #pragma unroll
        for (int nj = 0; nj < 4; nj++) {
            const int c = n0 + warpN * 32 + nj * 8 + 2 * Tj;
            float v0 = acc[mi][nj][0], v1 = acc[mi][nj][1];
            float v2 = acc[mi][nj][2], v3 = acc[mi][nj][3];
            if (bias) {
                float b0 = bias[c], b1 = bias[c + 1];
                v0 += b0; v1 += b1; v2 += b0; v3 += b1;
            }
            if (epi == 1) {
                v0 = gelu_f(v0); v1 = gelu_f(v1); v2 = gelu_f(v2); v3 = gelu_f(v3);
            } else if (epi == 2) {
                v0 += res[(size_t)r * N + c];
                v1 += res[(size_t)r * N + c + 1];
                v2 += res[(size_t)(r + 8) * N + c];
                v3 += res[(size_t)(r + 8) * N + c + 1];
            }
            *(float2*)&C[(size_t)r * N + c]       = make_float2(v0, v1);
            *(float2*)&C[(size_t)(r + 8) * N + c] = make_float2(v2, v3);
        }
    }
}

// ---------------------------------------------------------------------------
// TF32 GEMM (NT): C[M,N] = A[M,K] @ W[N,K]^T  (tied lm_head; R9 proven)
// ---------------------------------------------------------------------------
__global__ void __launch_bounds__(256) gemm_tf32_nt(
    const float* __restrict__ A, const float* __restrict__ W,
    float* __restrict__ C, int M, int N, int K)
{
    __shared__ float As[2][128][20];
    __shared__ float Bs[2][128][20];   // [n][k]

    const int m0 = blockIdx.x * 128;
    const int n0 = blockIdx.y * 128;
    const int tid  = threadIdx.x;
    const int lane = tid & 31;
    const int warp = tid >> 5;
    const int warpM = warp & 1;
    const int warpN = warp >> 1;
    const int Ti = lane >> 2;
    const int Tj = lane & 3;

    const int arow = tid >> 2;            // 0..63
    const int akq  = (tid & 3) * 4;       // 0,4,8,12

    int nB0 = n0 + arow;       if (nB0 >= N) nB0 = N - 1;
    int nB1 = n0 + arow + 64;  if (nB1 >= N) nB1 = N - 1;

    float acc[4][4][4];
    #pragma unroll
    for (int i = 0; i < 4; i++)
        #pragma unroll
        for (int j = 0; j < 4; j++)
            #pragma unroll
            for (int r = 0; r < 4; r++) acc[i][j][r] = 0.f;

    const int nk = K / 16;

    {
        const float* ap = A + (size_t)(m0 + arow) * K + akq;
        cp_async16(&As[0][arow][akq],      ap);
        cp_async16(&As[0][arow + 64][akq], ap + (size_t)64 * K);
        cp_async16(&Bs[0][arow][akq],      W + (size_t)nB0 * K + akq);
        cp_async16(&Bs[0][arow + 64][akq], W + (size_t)nB1 * K + akq);
        CP_COMMIT();
    }

    for (int kt = 0; kt < nk; kt++) {
        if (kt + 1 < nk) {
            int s = (kt + 1) & 1;
            int k0 = (kt + 1) * 16;
            const float* ap = A + (size_t)(m0 + arow) * K + k0 + akq;
            cp_async16(&As[s][arow][akq],      ap);
            cp_async16(&As[s][arow + 64][akq], ap + (size_t)64 * K);
            cp_async16(&Bs[s][arow][akq],      W + (size_t)nB0 * K + k0 + akq);
            cp_async16(&Bs[s][arow + 64][akq], W + (size_t)nB1 * K + k0 + akq);
            CP_COMMIT();
            CP_WAIT(1);
        } else {
            CP_WAIT(0);
        }
        __syncthreads();

        const int s = kt & 1;
        #pragma unroll
        for (int ks = 0; ks < 2; ks++) {
            const int k0 = ks * 8;
            unsigned af[4][4], bf[4][2];
            #pragma unroll
            for (int mi = 0; mi < 4; mi++) {
                int rb = warpM * 64 + mi * 16;
                af[mi][0] = f2tf32(As[s][rb + Ti][k0 + Tj]);
                af[mi][1] = f2tf32(As[s][rb + Ti + 8][k0 + Tj]);
                af[mi][2] = f2tf32(As[s][rb + Ti][k0 + Tj + 4]);
                af[mi][3] = f2tf32(As[s][rb + Ti + 8][k0 + Tj + 4]);
            }
            #pragma unroll
            for (int nj = 0; nj < 4; nj++) {
                int cb = warpN * 32 + nj * 8;
                bf[nj][0] = f2tf32(Bs[s][cb + Ti][k0 + Tj]);
                bf[nj][1] = f2tf32(Bs[s][cb + Ti][k0 + Tj + 4]);
            }
            #pragma unroll
            for (int mi = 0; mi < 4; mi++)
                #pragma unroll
                for (int nj = 0; nj < 4; nj++)
                    mma_tf32(acc[mi][nj], af[mi], bf[nj]);
        }
        __syncthreads();
    }

    #pragma unroll
    for (int mi = 0; mi < 4; mi++) {
        const int r = m0 + warpM * 64 + mi * 16 + Ti;
        #pragma unroll
        for (int nj = 0; nj < 4; nj++) {
            const int c = n0 + warpN * 32 + nj * 8 + 2 * Tj;
            if (c < N) {
                C[(size_t)r * N + c]       = acc[mi][nj][0];
                C[(size_t)(r + 8) * N + c] = acc[mi][nj][2];
            }
            if (c + 1 < N) {
                C[(size_t)r * N + c + 1]       = acc[mi][nj][1];
                C[(size_t)(r + 8) * N + c + 1] = acc[mi][nj][3];
            }
        }
    }
}

// ---------------------------------------------------------------------------
// Causal flash attention, split-K partials. grid (TT/AQ, B*H, NSPL).
// Empty splits write l=0/mx=-1e30 (merge weight exp(-1e30-m)=0).
// ---------------------------------------------------------------------------
#define AQ 64   // queries (=threads) per block
__global__ void __launch_bounds__(AQ) attn_partial(const float* __restrict__ qkv,
                                                   float* __restrict__ part,
                                                   float* __restrict__ ml)
{
    const int bh = blockIdx.y;
    const int b  = bh / HH;
    const int h  = bh % HH;
    const int qi = (gridDim.x - 1) - blockIdx.x;   // heavy blocks first
    const int sp = blockIdx.z;
    const int t  = qi * AQ + threadIdx.x;
    const float scale = 0.125f;  // 1/sqrt(64)

    const int ntiles = (qi * AQ + AQ) / 32;        // total causal key tiles
    const int q4 = (ntiles + NSPL - 1) / NSPL;
    int tb = sp * q4;       if (tb > ntiles) tb = ntiles;
    int te = (sp + 1) * q4; if (te > ntiles) te = ntiles;
    const int kb_begin = tb * 32;
    const int kb_end   = te * 32;

    float q[64];
    {
        const float* qp = qkv + (size_t)(b * TT + t) * (3 * DD) + h * HD;
        #pragma unroll
        for (int i = 0; i < 64; i += 4) {
            float4 v = *(const float4*)(qp + i);
            q[i + 0] = v.x * scale; q[i + 1] = v.y * scale;
            q[i + 2] = v.z * scale; q[i + 3] = v.w * scale;
        }
    }
    float acc[64];
    #pragma unroll
    for (int i = 0; i < 64; i++) acc[i] = 0.f;
    float mx = -1e30f, l = 0.f;

    __shared__ float Ks[32][64];
    __shared__ float Vs[32][64];

    for (int kb = kb_begin; kb < kb_end; kb += 32) {
        #pragma unroll
        for (int s = 0; s < 8; s++) {
            int f = threadIdx.x + s * AQ;    // 0..511
            int r = f >> 4;
            int c = (f & 15) * 4;
            const float* kp = qkv + (size_t)(b * TT + kb + r) * (3 * DD) + DD + h * HD + c;
            *(float4*)&Ks[r][c] = *(const float4*)kp;
            *(float4*)&Vs[r][c] = *(const float4*)(kp + DD);
        }
        __syncthreads();

        int jn = t - kb + 1;                 // valid keys in this 32-tile
        if (jn > 32) jn = 32;
        for (int j0 = 0; j0 < 32; j0 += 8) {
            if (j0 >= jn) break;
            float sc[8];
            #pragma unroll
            for (int j = 0; j < 8; j++) {
                const float* kr = &Ks[j0 + j][0];
                float a0 = 0.f, a1 = 0.f, a2 = 0.f, a3 = 0.f;
                #pragma unroll
                for (int i = 0; i < 64; i += 16) {
                    float4 k0 = *(const float4*)(kr + i);
                    float4 k1 = *(const float4*)(kr + i + 4);
                    float4 k2 = *(const float4*)(kr + i + 8);
                    float4 k3 = *(const float4*)(kr + i + 12);
                    a0 = fmaf(q[i+ 0], k0.x, a0); a0 = fmaf(q[i+ 1], k0.y, a0);
                    a0 = fmaf(q[i+ 2], k0.z, a0); a0 = fmaf(q[i+ 3], k0.w, a0);
                    a1 = fmaf(q[i+ 4], k1.x, a1); a1 = fmaf(q[i+ 5], k1.y, a1);
                    a1 = fmaf(q[i+ 6], k1.z, a1); a1 = fmaf(q[i+ 7], k1.w, a1);
                    a2 = fmaf(q[i+ 8], k2.x, a2); a2 = fmaf(q[i+ 9], k2.y, a2);
                    a2 = fmaf(q[i+10], k2.z, a2); a2 = fmaf(q[i+11], k2.w, a2);
                    a3 = fmaf(q[i+12], k3.x, a3); a3 = fmaf(q[i+13], k3.y, a3);
                    a3 = fmaf(q[i+14], k3.z, a3); a3 = fmaf(q[i+15], k3.w, a3);
                }
                sc[j] = (a0 + a1) + (a2 + a3);
                if (kb + j0 + j > t) sc[j] = -1e30f;   // causal mask
            }
            float mt = sc[0];
            #pragma unroll
            for (int j = 1; j < 8; j++) mt = fmaxf(mt, sc[j]);
            if (mt > mx) {
                float corr = __expf(mx - mt);
                l *= corr;
                #pragma unroll
                for (int i = 0; i < 64; i++) acc[i] *= corr;
                mx = mt;
            }
            float p[8];
            #pragma unroll
            for (int j = 0; j < 8; j++) {
                p[j] = __expf(sc[j] - mx);
                l += p[j];
            }
            #pragma unroll
            for (int j = 0; j < 8; j++) {
                const float* vr = &Vs[j0 + j][0];
                #pragma unroll
                for (int i = 0; i < 64; i += 4) {
                    float4 vv = *(const float4*)(vr + i);
                    acc[i + 0] = fmaf(p[j], vv.x, acc[i + 0]);
                    acc[i + 1] = fmaf(p[j], vv.y, acc[i + 1]);
                    acc[i + 2] = fmaf(p[j], vv.z, acc[i + 2]);
                    acc[i + 3] = fmaf(p[j], vv.w, acc[i + 3]);
                }
            }
        }
        __syncthreads();
    }

    // write unnormalized partial + (mx, l)
    const size_t base = (size_t)(sp * BB * HH + bh) * TT + t;
    float* pp = part + base * 64;
    #pragma unroll
    for (int i = 0; i < 64; i += 4) {
        float4 o;
        o.x = acc[i + 0]; o.y = acc[i + 1];
        o.z = acc[i + 2]; o.w = acc[i + 3];
        *(float4*)(pp + i) = o;
    }
    ml[base * 2]     = mx;
    ml[base * 2 + 1] = l;
}

// ---------------------------------------------------------------------------
// Merge the NSPL split-K partials (exact flash combine).
// ---------------------------------------------------------------------------
__global__ void __launch_bounds__(256) attn_merge(const float* __restrict__ part,
                                                  const float* __restrict__ ml,
                                                  float* __restrict__ y)
{
    int idx = blockIdx.x * 256 + threadIdx.x;   // 0 .. B*H*T*16-1
    int d4  = (idx & 15) * 4;
    int tt  = (idx >> 4) & (TT - 1);
    int bh  = idx >> 14;
    int b   = bh / HH;
    int h   = bh % HH;

    size_t base[NSPL];
    float ms[NSPL], ls[NSPL];
    float m = -1e30f;
    #pragma unroll
    for (int s = 0; s < NSPL; s++) {
        base[s] = (size_t)(s * BB * HH + bh) * TT + tt;
        ms[s] = ml[base[s] * 2];
        ls[s] = ml[base[s] * 2 + 1];
        m = fmaxf(m, ms[s]);
    }
    float denom = 0.f;
    float4 o = make_float4(0.f, 0.f, 0.f, 0.f);
    #pragma unroll
    for (int s = 0; s < NSPL; s++) {
        float w = __expf(ms[s] - m);
        denom += w * ls[s];
        float4 a = *(const float4*)(part + base[s] * 64 + d4);
        o.x += w * a.x; o.y += w * a.y; o.z += w * a.z; o.w += w * a.w;
    }
    float inv = 1.f / denom;
    o.x *= inv; o.y *= inv; o.z *= inv; o.w *= inv;
    *(float4*)(y + (size_t)(b * TT + tt) * DD + h * HD + d4) = o;
}

// ---------------------------------------------------------------------------
// Host launcher
// ---------------------------------------------------------------------------
extern "C" void kernel_launch(void* const* d_in, const int* in_sizes, int n_in,
                              void* d_out, int out_size)
{
    const int*   idx   = (const int*)  d_in[0];
    const float* wte   = (const float*)d_in[1];
    const float* wpe   = (const float*)d_in[2];
    const float* ln1w  = (const float*)d_in[3];
    const float* ln1b  = (const float*)d_in[4];
    const float* attnw = (const float*)d_in[5];
    const float* attnb = (const float*)d_in[6];
    const float* apw   = (const float*)d_in[7];
    const float* apb   = (const float*)d_in[8];
    const float* ln2w  = (const float*)d_in[9];
    const float* ln2b  = (const float*)d_in[10];
    const float* fcw   = (const float*)d_in[11];
    const float* fcb   = (const float*)d_in[12];
    const float* pw    = (const float*)d_in[13];
    const float* pb    = (const float*)d_in[14];
    const float* lnfw  = (const float*)d_in[15];
    const float* lnfb  = (const float*)d_in[16];
    float* out = (float*)d_out;

    float *x, *h, *qkv, *ffn, *part, *ml;
    cudaGetSymbolAddress((void**)&x,    g_x);
    cudaGetSymbolAddress((void**)&h,    g_h);
    cudaGetSymbolAddress((void**)&qkv,  g_qkv);
    cudaGetSymbolAddress((void**)&ffn,  g_ffn);
    cudaGetSymbolAddress((void**)&part, g_part);
    cudaGetSymbolAddress((void**)&ml,   g_ml);

    embed_kernel<<<MM, 256>>>(idx, wte, wpe, x);

    for (int l = 0; l < LL; l++) {
        ln_kernel<<<MM, 256>>>(x, ln1w + (size_t)l * DD, ln1b + (size_t)l * DD, h);
        // QKV: [M,D] @ [D,3D] + bias
        gemm_tf32_nn<<<dim3(MM / 128, 3 * DD / 128), 256>>>(
            h, attnw + (size_t)l * DD * 3 * DD, attnb + (size_t)l * 3 * DD,
            nullptr, qkv, MM, 3 * DD, DD, 0);
        // attention: split-K partials + exact merge
        attn_partial<<<dim3(TT / AQ, BB * HH, NSPL), AQ>>>(qkv, part, ml);
        attn_merge<<<BB * HH * TT * 16 / 256, 256>>>(part, ml, h);
        // attn proj: x = x + y @ pw + pb
        gemm_tf32_nn<<<dim3(MM / 128, DD / 128), 256>>>(
            h, apw + (size_t)l * DD * DD, apb + (size_t)l * DD,
            x, x, MM, DD, DD, 2);
        ln_kernel<<<MM, 256>>>(x, ln2w + (size_t)l * DD, ln2b + (size_t)l * DD, h);
        // FC + gelu
        gemm_tf32_nn<<<dim3(MM / 128, FF / 128), 256>>>(
            h, fcw + (size_t)l * DD * FF, fcb + (size_t)l * FF,
            nullptr, ffn, MM, FF, DD, 1);
        // proj: x = x + ffn @ ow + ob
        gemm_tf32_nn<<<dim3(MM / 128, DD / 128), 256>>>(
            ffn, pw + (size_t)l * FF * DD, pb + (size_t)l * DD,
            x, x, MM, DD, FF, 2);
    }

    ln_kernel<<<MM, 256>>>(x, lnfw, lnfb, h);
    gemm_tf32_nt<<<dim3(MM / 128, (VV + 127) / 128), 256>>>(
        h, wte, out, MM, VV, DD);
}